// round 8
// baseline (speedup 1.0000x reference)
#include <cuda_runtime.h>
#include <cuda_bf16.h>
#include <math.h>
#include <stdint.h>

#define NQ 6
#define NL 3

typedef uint32_t u32;
typedef unsigned short u16;

// ==================== device globals ====================
__device__ __align__(16) float g_Gr[64][64];
__device__ __align__(16) float g_Gi[64][64];
__device__ float g_G[3][64];
__device__ float g_d[3];
// W1 split into bf16 hi/lo, pre-swizzled per 64-k chunk tile (32 chunks x 4096 u16)
__device__ __align__(128) u16 g_w1hi[32 * 4096];
__device__ __align__(128) u16 g_w1lo[32 * 4096];

// tile layout: row r (0..63) x k (0..63) bf16; one 128B line per row, XOR swizzle
__device__ __host__ __forceinline__ u32 aoff(u32 r, u32 k) {
    return r * 128 + ((k * 2) ^ ((r & 7) << 4));
}

// ---- kernel 0: blocks 0-3 build evolution matrix; blocks 4-67 split W1 ----
__global__ __launch_bounds__(256) void precompute_kernel(const float* __restrict__ qw,
                                                         const float* __restrict__ Wq,
                                                         const float* __restrict__ bq,
                                                         const float* __restrict__ Wf,
                                                         const float* __restrict__ bf,
                                                         const float* __restrict__ W1) {
    const int t = threadIdx.x;
    if (blockIdx.x >= 4) {
        // W1 split: 64 blocks x 256 threads x 8 elems = 131072 = 64 x 2048
        const int base = ((blockIdx.x - 4) * 256 + t) * 8;
        #pragma unroll
        for (int e = 0; e < 8; e++) {
            const int idx = base + e;
            const int n = idx >> 11, k = idx & 2047;
            const float v = W1[idx];
            const u32 bv = __float_as_uint(v);
            const u16 hi = (u16)(bv >> 16);
            const float lo = v - __uint_as_float(bv & 0xFFFF0000u);
            u32 lw;
            asm("cvt.rn.bf16x2.f32 %0, %1, %2;" : "=r"(lw) : "f"(0.f), "f"(lo));
            const int c = k >> 6, kk = k & 63;
            const int pos = c * 4096 + n * 64 + (kk ^ ((n & 7) << 3));
            g_w1hi[pos] = hi;
            g_w1lo[pos] = (u16)lw;
        }
        return;
    }

    __shared__ float Mr[64][17];
    __shared__ float Mi[64][17];
    __shared__ float2 sU[NL * NQ][4];
    __shared__ float sA[3][NQ];
    const int col0 = blockIdx.x * 16;

    if (t < NL * NQ) {
        float phi = qw[t * 3 + 0], th = qw[t * 3 + 1], om = qw[t * 3 + 2];
        float s2, c2;  sincosf(0.5f * th, &s2, &c2);
        float spo, cpo; sincosf(0.5f * (phi + om), &spo, &cpo);
        float smo, cmo; sincosf(0.5f * (phi - om), &smo, &cmo);
        sU[t][0] = make_float2( cpo * c2, -spo * c2);
        sU[t][1] = make_float2(-cmo * s2, -smo * s2);
        sU[t][2] = make_float2( cmo * s2, -smo * s2);
        sU[t][3] = make_float2( cpo * c2,  spo * c2);
    }
    if (blockIdx.x == 0 && t >= 32 && t < 50) {
        int u = t - 32, j = u / 6, w = u % 6;
        float a = 0.f;
        for (int k = 0; k < 16; k++) a += Wf[j * 80 + 64 + k] * Wq[k * 6 + w];
        sA[j][w] = a;
    }
    for (int idx = t; idx < 1024; idx += 256) {
        int r = idx >> 4, c = idx & 15;
        Mr[r][c] = (r == col0 + c) ? 1.f : 0.f;
        Mi[r][c] = 0.f;
    }
    __syncthreads();

    for (int l = 0; l < NL; l++) {
        for (int w = 0; w < NQ; w++) {
            float2 u00 = sU[l * NQ + w][0], u01 = sU[l * NQ + w][1];
            float2 u10 = sU[l * NQ + w][2], u11 = sU[l * NQ + w][3];
            const int bit = 1 << (5 - w);
            for (int v = t; v < 512; v += 256) {
                int p = v >> 4, c = v & 15;
                int i = ((p & ~(bit - 1)) << 1) | (p & (bit - 1));
                int j = i | bit;
                float ar = Mr[i][c], ai = Mi[i][c], br = Mr[j][c], bi = Mi[j][c];
                Mr[i][c] = u00.x * ar - u00.y * ai + u01.x * br - u01.y * bi;
                Mi[i][c] = u00.x * ai + u00.y * ar + u01.x * bi + u01.y * br;
                Mr[j][c] = u10.x * ar - u10.y * ai + u11.x * br - u11.y * bi;
                Mi[j][c] = u10.x * ai + u10.y * ar + u11.x * bi + u11.y * br;
            }
            __syncthreads();
        }
        const int r = (l % (NQ - 1)) + 1;
        for (int w = 0; w < NQ; w++) {
            const int tq = (w + r) % NQ;
            const int cbit = 1 << (5 - w);
            const int tbit = 1 << (5 - tq);
            const int lo_b = cbit < tbit ? cbit : tbit;
            const int hi_b = cbit < tbit ? tbit : cbit;
            if (t < 256) {
                for (int v = t; v < 256; v += 256) {
                    int x = v >> 4, c = v & 15;
                    int t1 = ((x & ~(lo_b - 1)) << 1) | (x & (lo_b - 1));
                    int i0 = ((t1 & ~(hi_b - 1)) << 1) | (t1 & (hi_b - 1));
                    int i = i0 | cbit;
                    int j = i | tbit;
                    float tr = Mr[i][c]; Mr[i][c] = Mr[j][c]; Mr[j][c] = tr;
                    float ti = Mi[i][c]; Mi[i][c] = Mi[j][c]; Mi[j][c] = ti;
                }
            }
            __syncthreads();
        }
    }

    for (int idx = t; idx < 1024; idx += 256) {
        int r = idx >> 4, c = idx & 15;
        g_Gr[r][col0 + c] = Mr[r][c];
        g_Gi[r][col0 + c] = Mi[r][c];
    }
    if (blockIdx.x == 0) {
        for (int i = t; i < 192; i += 256) {
            int j = i >> 6, s = i & 63;
            float g = 0.f;
            #pragma unroll
            for (int w = 0; w < 6; w++)
                g += sA[j][w] * (((s >> (5 - w)) & 1) ? -1.f : 1.f);
            g_G[j][s] = g;
        }
        if (t < 3) {
            float v = bf[t];
            for (int k = 0; k < 16; k++) v += Wf[t * 80 + 64 + k] * bq[k];
            g_d[t] = v;
        }
    }
}

// ==================== fused GEMM + quantum ====================
#define KC 64
#define NCHUNK 32
#define ASLOT 16384          // A_HI 8K | A_LO 8K
#define BSLOT 16384          // B_HI 8K | B_LO 8K
#define RING_BYTES (2 * ASLOT + 3 * BSLOT)
#define GEMM_DSMEM (RING_BYTES + 1024)

__device__ __forceinline__ u32 smem_u32(const void* p) {
    u32 a;
    asm("{ .reg .u64 t; cvta.to.shared.u64 t, %1; cvt.u32.u64 %0, t; }" : "=r"(a) : "l"(p));
    return a;
}

#define LDMX4(r0, r1, r2, r3, addr) \
    asm volatile("ldmatrix.sync.aligned.m8n8.x4.shared.b16 {%0,%1,%2,%3}, [%4];" \
        : "=r"(r0), "=r"(r1), "=r"(r2), "=r"(r3) : "r"(addr))

#define MMA16816(d, a, b0, b1) \
    asm volatile("mma.sync.aligned.m16n8k16.row.col.f32.bf16.bf16.f32 " \
        "{%0,%1,%2,%3}, {%4,%5,%6,%7}, {%8,%9}, {%0,%1,%2,%3};" \
        : "+f"((d)[0]), "+f"((d)[1]), "+f"((d)[2]), "+f"((d)[3]) \
        : "r"((a)[0]), "r"((a)[1]), "r"((a)[2]), "r"((a)[3]), "r"(b0), "r"(b1))

__device__ __forceinline__ void cp16(u32 dst, const void* src) {
    asm volatile("cp.async.cg.shared.global [%0], [%1], 16;"
        :: "r"(dst), "l"((size_t)__cvta_generic_to_global(src)) : "memory");
}

// split 8 floats -> 16B bf16-hi + 16B bf16-lo vector stores
__device__ __forceinline__ void split8(u32 hi_addr, u32 lo_addr, float4 v0, float4 v1) {
    u32 b0 = __float_as_uint(v0.x), b1 = __float_as_uint(v0.y);
    u32 b2 = __float_as_uint(v0.z), b3 = __float_as_uint(v0.w);
    u32 b4 = __float_as_uint(v1.x), b5 = __float_as_uint(v1.y);
    u32 b6 = __float_as_uint(v1.z), b7 = __float_as_uint(v1.w);
    u32 h01 = __byte_perm(b0, b1, 0x7632);
    u32 h23 = __byte_perm(b2, b3, 0x7632);
    u32 h45 = __byte_perm(b4, b5, 0x7632);
    u32 h67 = __byte_perm(b6, b7, 0x7632);
    float l0 = v0.x - __uint_as_float(b0 & 0xFFFF0000u);
    float l1 = v0.y - __uint_as_float(b1 & 0xFFFF0000u);
    float l2 = v0.z - __uint_as_float(b2 & 0xFFFF0000u);
    float l3 = v0.w - __uint_as_float(b3 & 0xFFFF0000u);
    float l4 = v1.x - __uint_as_float(b4 & 0xFFFF0000u);
    float l5 = v1.y - __uint_as_float(b5 & 0xFFFF0000u);
    float l6 = v1.z - __uint_as_float(b6 & 0xFFFF0000u);
    float l7 = v1.w - __uint_as_float(b7 & 0xFFFF0000u);
    u32 L01, L23, L45, L67;
    asm("cvt.rn.bf16x2.f32 %0, %1, %2;" : "=r"(L01) : "f"(l1), "f"(l0));
    asm("cvt.rn.bf16x2.f32 %0, %1, %2;" : "=r"(L23) : "f"(l3), "f"(l2));
    asm("cvt.rn.bf16x2.f32 %0, %1, %2;" : "=r"(L45) : "f"(l5), "f"(l4));
    asm("cvt.rn.bf16x2.f32 %0, %1, %2;" : "=r"(L67) : "f"(l7), "f"(l6));
    asm volatile("st.shared.v4.b32 [%0], {%1,%2,%3,%4};"
        :: "r"(hi_addr), "r"(h01), "r"(h23), "r"(h45), "r"(h67) : "memory");
    asm volatile("st.shared.v4.b32 [%0], {%1,%2,%3,%4};"
        :: "r"(lo_addr), "r"(L01), "r"(L23), "r"(L45), "r"(L67) : "memory");
}

__global__ __launch_bounds__(128, 2) void fused_kernel(const float* __restrict__ xc,
                                                       const float* __restrict__ b1,
                                                       const float* __restrict__ Wf,
                                                       const float* __restrict__ xq,
                                                       float* __restrict__ out) {
    extern __shared__ char dyn_smem[];
    __shared__ float sG[192];
    __shared__ float sWf[192];
    __shared__ float sB1[64];
    __shared__ float sd[4];
    __shared__ float sOut[192];

    const u32 sb = smem_u32(dyn_smem);
    const u32 ring = (sb + 1023u) & ~1023u;
    char* rbase = dyn_smem + (ring - sb);
    const u32 Abase = ring;
    const u32 Bbase = ring + 2 * ASLOT;

    const int tid = threadIdx.x;
    const int lane = tid & 31;
    const int warp = tid >> 5;
    const int row0 = blockIdx.x * 64;
    const int m0 = (warp & 1) * 32;
    const int n0 = (warp >> 1) * 32;

    // prologue smem tables
    for (int i = tid; i < 192; i += 128) {
        sG[i]  = ((const float*)g_G)[i];
        sWf[i] = Wf[(i >> 6) * 80 + (i & 63)];
        sOut[i] = 0.f;
    }
    if (tid < 64) sB1[tid] = b1[tid];
    if (tid < 3) sd[tid] = g_d[tid];

    // loader mapping: row = tid>>1, k-half = (tid&1)*32
    const int lr = tid >> 1;
    const int lh = (tid & 1) * 32;
    const float* xrow = xc + (size_t)(row0 + lr) * 2048 + lh;

    float4 pa[8];

#define LOAD_A(chunk) do { \
    const float4* p = (const float4*)(xrow + (chunk) * 64); \
    _Pragma("unroll") for (int j = 0; j < 8; j++) pa[j] = p[j]; } while (0)

#define STORE_A(Ab) do { \
    _Pragma("unroll") for (int j = 0; j < 4; j++) { \
        u32 o = aoff((u32)lr, (u32)(lh + 8 * j)); \
        split8((Ab) + o, (Ab) + 8192 + o, pa[2 * j], pa[2 * j + 1]); \
    } } while (0)

#define LOAD_B(chunk, Bb) do { \
    const char* shp = (const char*)g_w1hi + (size_t)(chunk) * 8192 + tid * 64; \
    const char* slp = (const char*)g_w1lo + (size_t)(chunk) * 8192 + tid * 64; \
    _Pragma("unroll") for (int j = 0; j < 4; j++) { \
        cp16((Bb) + tid * 64 + j * 16, shp + j * 16); \
        cp16((Bb) + 8192 + tid * 64 + j * 16, slp + j * 16); \
    } } while (0)

    // fragment address components (same mapping for A and B)
    const u32 arow = (u32)((lane & 7) + ((lane >> 3) & 1) * 8);
    const u32 akof = (u32)((lane >> 4) * 8);
    const u32 brow = arow;
    const u32 bkof = akof;

    float acc[2][4][4];
    #pragma unroll
    for (int mt = 0; mt < 2; mt++)
        #pragma unroll
        for (int nt = 0; nt < 4; nt++)
            #pragma unroll
            for (int e = 0; e < 4; e++) acc[mt][nt][e] = 0.f;

    // prologue pipeline
    LOAD_A(0);
    LOAD_B(0, Bbase);
    asm volatile("cp.async.commit_group;" ::: "memory");
    LOAD_B(1, Bbase + BSLOT);
    asm volatile("cp.async.commit_group;" ::: "memory");
    STORE_A(Abase);
    LOAD_A(1);
    asm volatile("cp.async.wait_group 1;" ::: "memory");
    __syncthreads();

    #pragma unroll 1
    for (int i = 0; i < NCHUNK; i++) {
        const u32 Ab = Abase + (u32)(i & 1) * ASLOT;
        const u32 Bb = Bbase + (u32)(i % 3) * BSLOT;

        #pragma unroll
        for (int ks = 0; ks < 4; ks++) {
            u32 ah[2][4], al[2][4], bh[2][4], bl[2][4];
            #pragma unroll
            for (int mt = 0; mt < 2; mt++) {
                u32 a_ = Ab + aoff((u32)(m0 + mt * 16) + arow, (u32)(ks * 16) + akof);
                LDMX4(ah[mt][0], ah[mt][1], ah[mt][2], ah[mt][3], a_);
                LDMX4(al[mt][0], al[mt][1], al[mt][2], al[mt][3], a_ + 8192);
            }
            #pragma unroll
            for (int g = 0; g < 2; g++) {
                u32 b_ = Bb + aoff((u32)(n0 + g * 16) + brow, (u32)(ks * 16) + bkof);
                LDMX4(bh[g][0], bh[g][1], bh[g][2], bh[g][3], b_);
                LDMX4(bl[g][0], bl[g][1], bl[g][2], bl[g][3], b_ + 8192);
            }
            // A-style ldmatrix ordering: frag0=(n0-7,kLo) frag1=(n8-15,kLo)
            //                            frag2=(n0-7,kHi) frag3=(n8-15,kHi)
            // -> MMA b-operand pair is {frag[p], frag[p+2]} with p = nt&1.
            #pragma unroll
            for (int mt = 0; mt < 2; mt++)
                #pragma unroll
                for (int nt = 0; nt < 4; nt++) {
                    const int g = nt >> 1, p = nt & 1;
                    MMA16816(acc[mt][nt], ah[mt], bh[g][p], bh[g][p + 2]);
                    MMA16816(acc[mt][nt], ah[mt], bl[g][p], bl[g][p + 2]);
                    MMA16816(acc[mt][nt], al[mt], bh[g][p], bh[g][p + 2]);
                }
        }

        if (i < 31) STORE_A(Abase + (u32)((i + 1) & 1) * ASLOT);
        if (i < 30) {
            LOAD_A(i + 2);
            LOAD_B(i + 2, Bbase + (u32)((i + 2) % 3) * BSLOT);
            asm volatile("cp.async.commit_group;" ::: "memory");
            asm volatile("cp.async.wait_group 1;" ::: "memory");
        } else if (i == 30) {
            asm volatile("cp.async.wait_group 0;" ::: "memory");
        }
        __syncthreads();
    }

    // ---- gemm fold: relu(acc + b1) . Wf ----
    // acc[mt][nt] covers columns n0 + (nt>>1)*16 + (nt&1)*8 == n0 + nt*8
    float og[2][2][3];
    #pragma unroll
    for (int mt = 0; mt < 2; mt++)
        #pragma unroll
        for (int h = 0; h < 2; h++)
            #pragma unroll
            for (int j = 0; j < 3; j++) og[mt][h][j] = 0.f;

    #pragma unroll
    for (int mt = 0; mt < 2; mt++)
        #pragma unroll
        for (int nt = 0; nt < 4; nt++) {
            const int c0 = n0 + nt * 8 + 2 * (lane & 3);
            const int c1 = c0 + 1;
            const float bb0 = sB1[c0], bb1 = sB1[c1];
            float v00 = acc[mt][nt][0] + bb0; v00 = v00 > 0.f ? v00 : 0.f;
            float v01 = acc[mt][nt][1] + bb1; v01 = v01 > 0.f ? v01 : 0.f;
            float v10 = acc[mt][nt][2] + bb0; v10 = v10 > 0.f ? v10 : 0.f;
            float v11 = acc[mt][nt][3] + bb1; v11 = v11 > 0.f ? v11 : 0.f;
            #pragma unroll
            for (int j = 0; j < 3; j++) {
                og[mt][0][j] += v00 * sWf[j * 64 + c0] + v01 * sWf[j * 64 + c1];
                og[mt][1][j] += v10 * sWf[j * 64 + c0] + v11 * sWf[j * 64 + c1];
            }
        }
    #pragma unroll
    for (int mt = 0; mt < 2; mt++)
        #pragma unroll
        for (int h = 0; h < 2; h++)
            #pragma unroll
            for (int j = 0; j < 3; j++) {
                og[mt][h][j] += __shfl_xor_sync(0xFFFFFFFFu, og[mt][h][j], 1);
                og[mt][h][j] += __shfl_xor_sync(0xFFFFFFFFu, og[mt][h][j], 2);
            }
    if ((lane & 3) == 0) {
        #pragma unroll
        for (int mt = 0; mt < 2; mt++) {
            const int r = m0 + mt * 16 + (lane >> 2);
            #pragma unroll
            for (int j = 0; j < 3; j++) {
                atomicAdd(&sOut[r * 3 + j], og[mt][0][j]);
                atomicAdd(&sOut[(r + 8) * 3 + j], og[mt][1][j]);
            }
        }
    }

    // ---- copy G tables into the dead A-ring ----
    float* sGr = (float*)rbase;            // 16KB
    float* sGi = sGr + 4096;               // 16KB
    {
        const float4* gr4 = (const float4*)g_Gr;
        const float4* gi4 = (const float4*)g_Gi;
        float4* dr = (float4*)sGr;
        float4* di = (float4*)sGi;
        for (int i = tid; i < 1024; i += 128) { dr[i] = gr4[i]; di[i] = gi4[i]; }
    }
    __syncthreads();

    // ---- quantum: 2 threads per sample ----
    float q0 = 0.f, q1 = 0.f, q2 = 0.f;
    const int sl = tid >> 1;
    const int half = tid & 1;
    {
        const int sample = row0 + sl;
        float csq[NQ], snq[NQ];
        #pragma unroll
        for (int q = 0; q < NQ; q++) sincosf(0.5f * xq[sample * NQ + q], &snq[q], &csq[q]);

        float a[64];
        a[0] = csq[0]; a[1] = snq[0];
        #pragma unroll
        for (int q = 1; q < NQ; q++) {
            const int n = 1 << q;
            #pragma unroll 32
            for (int j = n - 1; j >= 0; j--) {
                float v = a[j];
                a[2 * j]     = v * csq[q];
                a[2 * j + 1] = v * snq[q];
            }
        }

        const int s0 = half * 32;
        #pragma unroll 2
        for (int ss = 0; ss < 32; ss++) {
            const int s = s0 + ss;
            const float4* gr = (const float4*)(sGr + s * 64);
            const float4* gi = (const float4*)(sGi + s * 64);
            float yr0 = 0.f, yr1 = 0.f, yi0 = 0.f, yi1 = 0.f;
            #pragma unroll
            for (int t4 = 0; t4 < 16; t4++) {
                float4 g1 = gr[t4], g2 = gi[t4];
                const float* av = &a[t4 * 4];
                yr0 += g1.x * av[0]; yr1 += g1.y * av[1];
                yr0 += g1.z * av[2]; yr1 += g1.w * av[3];
                yi0 += g2.x * av[0]; yi1 += g2.y * av[1];
                yi0 += g2.z * av[2]; yi1 += g2.w * av[3];
            }
            float yr = yr0 + yr1, yi = yi0 + yi1;
            float p = yr * yr + yi * yi;
            q0 += p * sG[s];
            q1 += p * sG[64 + s];
            q2 += p * sG[128 + s];
        }
        q0 += __shfl_xor_sync(0xFFFFFFFFu, q0, 1);
        q1 += __shfl_xor_sync(0xFFFFFFFFu, q1, 1);
        q2 += __shfl_xor_sync(0xFFFFFFFFu, q2, 1);
    }

    if (half == 0) {
        const size_t o = (size_t)(row0 + sl) * 3;
        out[o + 0] = sOut[sl * 3 + 0] + q0 + sd[0];
        out[o + 1] = sOut[sl * 3 + 1] + q1 + sd[1];
        out[o + 2] = sOut[sl * 3 + 2] + q2 + sd[2];
    }
}

// ==================== launch ====================
extern "C" void kernel_launch(void* const* d_in, const int* in_sizes, int n_in,
                              void* d_out, int out_size) {
    const float* xc = (const float*)d_in[0];
    const float* xq = (const float*)d_in[1];
    const float* W1 = (const float*)d_in[2];
    const float* b1 = (const float*)d_in[3];
    const float* qw = (const float*)d_in[4];
    const float* Wq = (const float*)d_in[5];
    const float* bq = (const float*)d_in[6];
    const float* Wf = (const float*)d_in[7];
    const float* bf = (const float*)d_in[8];
    float* out = (float*)d_out;

    const int B = in_sizes[0] / 2048;  // 16384

    static int configured = 0;
    if (!configured) {
        cudaFuncSetAttribute(fused_kernel, cudaFuncAttributeMaxDynamicSharedMemorySize, GEMM_DSMEM);
        configured = 1;
    }

    precompute_kernel<<<68, 256>>>(qw, Wq, bq, Wf, bf, W1);
    fused_kernel<<<B / 64, 128, GEMM_DSMEM>>>(xc, b1, Wf, xq, out);
}

// round 9
// speedup vs baseline: 1.1615x; 1.1615x over previous
#include <cuda_runtime.h>
#include <cuda_bf16.h>
#include <math.h>
#include <stdint.h>

#define NQ 6
#define NL 3

typedef uint32_t u32;

// ==================== quantum tables ====================
__device__ __align__(16) float g_Gr[64][64];
__device__ __align__(16) float g_Gi[64][64];
__device__ float g_G[3][64];
__device__ float g_d[3];

// ---- kernel 0: build 64x64 evolution matrix (4 blocks x 16 columns) ----
__global__ __launch_bounds__(256) void precompute_kernel(const float* __restrict__ qw,
                                                         const float* __restrict__ Wq,
                                                         const float* __restrict__ bq,
                                                         const float* __restrict__ Wf,
                                                         const float* __restrict__ bf) {
    __shared__ float Mr[64][17];
    __shared__ float Mi[64][17];
    __shared__ float2 sU[NL * NQ][4];
    __shared__ float sA[3][NQ];
    const int t = threadIdx.x;
    const int col0 = blockIdx.x * 16;

    if (t < NL * NQ) {
        float phi = qw[t * 3 + 0], th = qw[t * 3 + 1], om = qw[t * 3 + 2];
        float s2, c2;  sincosf(0.5f * th, &s2, &c2);
        float spo, cpo; sincosf(0.5f * (phi + om), &spo, &cpo);
        float smo, cmo; sincosf(0.5f * (phi - om), &smo, &cmo);
        sU[t][0] = make_float2( cpo * c2, -spo * c2);
        sU[t][1] = make_float2(-cmo * s2, -smo * s2);
        sU[t][2] = make_float2( cmo * s2, -smo * s2);
        sU[t][3] = make_float2( cpo * c2,  spo * c2);
    }
    if (blockIdx.x == 0 && t >= 32 && t < 50) {
        int u = t - 32, j = u / 6, w = u % 6;
        float a = 0.f;
        for (int k = 0; k < 16; k++) a += Wf[j * 80 + 64 + k] * Wq[k * 6 + w];
        sA[j][w] = a;
    }
    for (int idx = t; idx < 1024; idx += 256) {
        int r = idx >> 4, c = idx & 15;
        Mr[r][c] = (r == col0 + c) ? 1.f : 0.f;
        Mi[r][c] = 0.f;
    }
    __syncthreads();

    for (int l = 0; l < NL; l++) {
        for (int w = 0; w < NQ; w++) {
            float2 u00 = sU[l * NQ + w][0], u01 = sU[l * NQ + w][1];
            float2 u10 = sU[l * NQ + w][2], u11 = sU[l * NQ + w][3];
            const int bit = 1 << (5 - w);
            for (int v = t; v < 512; v += 256) {
                int p = v >> 4, c = v & 15;
                int i = ((p & ~(bit - 1)) << 1) | (p & (bit - 1));
                int j = i | bit;
                float ar = Mr[i][c], ai = Mi[i][c], br = Mr[j][c], bi = Mi[j][c];
                Mr[i][c] = u00.x * ar - u00.y * ai + u01.x * br - u01.y * bi;
                Mi[i][c] = u00.x * ai + u00.y * ar + u01.x * bi + u01.y * br;
                Mr[j][c] = u10.x * ar - u10.y * ai + u11.x * br - u11.y * bi;
                Mi[j][c] = u10.x * ai + u10.y * ar + u11.x * bi + u11.y * br;
            }
            __syncthreads();
        }
        const int r = (l % (NQ - 1)) + 1;
        for (int w = 0; w < NQ; w++) {
            const int tq = (w + r) % NQ;
            const int cbit = 1 << (5 - w);
            const int tbit = 1 << (5 - tq);
            const int lo_b = cbit < tbit ? cbit : tbit;
            const int hi_b = cbit < tbit ? tbit : cbit;
            for (int v = t; v < 256; v += 256) {
                int x = v >> 4, c = v & 15;
                int t1 = ((x & ~(lo_b - 1)) << 1) | (x & (lo_b - 1));
                int i0 = ((t1 & ~(hi_b - 1)) << 1) | (t1 & (hi_b - 1));
                int i = i0 | cbit;
                int j = i | tbit;
                float tr = Mr[i][c]; Mr[i][c] = Mr[j][c]; Mr[j][c] = tr;
                float ti = Mi[i][c]; Mi[i][c] = Mi[j][c]; Mi[j][c] = ti;
            }
            __syncthreads();
        }
    }

    for (int idx = t; idx < 1024; idx += 256) {
        int r = idx >> 4, c = idx & 15;
        g_Gr[r][col0 + c] = Mr[r][c];
        g_Gi[r][col0 + c] = Mi[r][c];
    }
    if (blockIdx.x == 0) {
        for (int i = t; i < 192; i += 256) {
            int j = i >> 6, s = i & 63;
            float g = 0.f;
            #pragma unroll
            for (int w = 0; w < 6; w++)
                g += sA[j][w] * (((s >> (5 - w)) & 1) ? -1.f : 1.f);
            g_G[j][s] = g;
        }
        if (t < 3) {
            float v = bf[t];
            for (int k = 0; k < 16; k++) v += Wf[t * 80 + 64 + k] * bq[k];
            g_d[t] = v;
        }
    }
}

// ==================== fused GEMM (mma.sync bf16-split) + quantum epilogue ====================
#define KC 32
#define NCHUNK 64
#define BUF_A_HI 0
#define BUF_A_LO 4096
#define BUF_B_HI 8192
#define BUF_B_LO 12288
#define BUFSZ 16384
#define RING (3 * BUFSZ)
#define GEMM_DSMEM (1024 + RING)

__device__ __forceinline__ u32 smem_u32(const void* p) {
    u32 a;
    asm("{ .reg .u64 t; cvta.to.shared.u64 t, %1; cvt.u32.u64 %0, t; }" : "=r"(a) : "l"(p));
    return a;
}

// XOR-swizzled offset for a [rows][KC] bf16 tile packed 2 rows per 128B line.
__device__ __forceinline__ u32 aoff(u32 row, u32 k) {
    u32 o = ((row >> 1) << 7) | ((row & 1) << 6) | (k << 1);
    return o ^ (((row >> 1) & 7) << 4);
}

#define LDMX4(r0, r1, r2, r3, addr) \
    asm volatile("ldmatrix.sync.aligned.m8n8.x4.shared.b16 {%0,%1,%2,%3}, [%4];" \
        : "=r"(r0), "=r"(r1), "=r"(r2), "=r"(r3) : "r"(addr))

#define MMA16816(d, a, b0, b1) \
    asm volatile("mma.sync.aligned.m16n8k16.row.col.f32.bf16.bf16.f32 " \
        "{%0,%1,%2,%3}, {%4,%5,%6,%7}, {%8,%9}, {%0,%1,%2,%3};" \
        : "+f"((d)[0]), "+f"((d)[1]), "+f"((d)[2]), "+f"((d)[3]) \
        : "r"((a)[0]), "r"((a)[1]), "r"((a)[2]), "r"((a)[3]), "r"(b0), "r"(b1))

__device__ __forceinline__ void split4(u32 hi_addr, u32 lo_addr, float4 v) {
    u32 b0 = __float_as_uint(v.x), b1 = __float_as_uint(v.y);
    u32 b2 = __float_as_uint(v.z), b3 = __float_as_uint(v.w);
    u32 h01 = __byte_perm(b0, b1, 0x7632);
    u32 h23 = __byte_perm(b2, b3, 0x7632);
    float l0 = v.x - __uint_as_float(b0 & 0xFFFF0000u);
    float l1 = v.y - __uint_as_float(b1 & 0xFFFF0000u);
    float l2 = v.z - __uint_as_float(b2 & 0xFFFF0000u);
    float l3 = v.w - __uint_as_float(b3 & 0xFFFF0000u);
    u32 L01, L23;
    asm("cvt.rn.bf16x2.f32 %0, %1, %2;" : "=r"(L01) : "f"(l1), "f"(l0));
    asm("cvt.rn.bf16x2.f32 %0, %1, %2;" : "=r"(L23) : "f"(l3), "f"(l2));
    asm volatile("st.shared.v2.b32 [%0], {%1,%2};" :: "r"(hi_addr), "r"(h01), "r"(h23) : "memory");
    asm volatile("st.shared.v2.b32 [%0], {%1,%2};" :: "r"(lo_addr), "r"(L01), "r"(L23) : "memory");
}

__global__ __launch_bounds__(128, 3) void fused_kernel(const float* __restrict__ xc,
                                                       const float* __restrict__ W1,
                                                       const float* __restrict__ b1,
                                                       const float* __restrict__ Wf,
                                                       const float* __restrict__ xq,
                                                       float* __restrict__ out) {
    extern __shared__ char dyn_smem[];
    __shared__ float sG[192];
    __shared__ float sWf[192];
    __shared__ float sB1[64];
    __shared__ float sd[4];
    __shared__ float sQ[192];

    const u32 sb = smem_u32(dyn_smem);
    const u32 ring = (sb + 1023u) & ~1023u;
    char* rbase = dyn_smem + (ring - sb);

    const int tid = threadIdx.x;
    const int lane = tid & 31;
    const int warp = tid >> 5;
    const int row0 = blockIdx.x * 64;
    const int m0 = warp * 16;

    // small tables (static smem)
    for (int i = tid; i < 192; i += 128) {
        sG[i]  = ((const float*)g_G)[i];
        sWf[i] = Wf[(i >> 6) * 80 + (i & 63)];
    }
    if (tid < 64) sB1[tid] = b1[tid];
    if (tid < 3) sd[tid] = g_d[tid];

    // loader coords: 512 float4 per matrix per chunk, 4 per thread
    int lrow[4], lk[4];
    #pragma unroll
    for (int g = 0; g < 4; g++) {
        int f = g * 128 + tid;
        lrow[g] = f >> 3;
        lk[g] = (f & 7) * 4;
    }

    float4 pa[4], pb[4];
    float acc[8][4];
    #pragma unroll
    for (int nt = 0; nt < 8; nt++)
        #pragma unroll
        for (int e = 0; e < 4; e++) acc[nt][e] = 0.f;

    const u32 arow = (u32)(m0 + (lane & 7) + ((lane >> 3) & 1) * 8);
    const u32 akof = (u32)((lane >> 4) * 8);
    const u32 brow_base = (u32)((lane & 7) + (lane >> 4) * 8);
    const u32 bkof = (u32)(((lane >> 3) & 1) * 8);

#define LOAD_CHUNK(kc) do { \
    _Pragma("unroll") \
    for (int g = 0; g < 4; g++) { \
        pa[g] = *(const float4*)(xc + (size_t)(row0 + lrow[g]) * 2048 + (kc) + lk[g]); \
        pb[g] = *(const float4*)(W1 + (size_t)lrow[g] * 2048 + (kc) + lk[g]); \
    } } while (0)

#define STORE_CHUNK(bufb) do { \
    _Pragma("unroll") \
    for (int g = 0; g < 4; g++) { \
        u32 o = aoff((u32)lrow[g], (u32)lk[g]); \
        split4((bufb) + BUF_A_HI + o, (bufb) + BUF_A_LO + o, pa[g]); \
        split4((bufb) + BUF_B_HI + o, (bufb) + BUF_B_LO + o, pb[g]); \
    } } while (0)

    LOAD_CHUNK(0);
    STORE_CHUNK(ring);
    LOAD_CHUNK(KC);
    STORE_CHUNK(ring + BUFSZ);
    LOAD_CHUNK(2 * KC);
    __syncthreads();

    #pragma unroll 1
    for (int i = 0; i < NCHUNK; i++) {
        if (i + 2 < NCHUNK) {
            STORE_CHUNK(ring + ((i + 2) % 3) * BUFSZ);
        }
        if (i + 3 < NCHUNK) {
            LOAD_CHUNK((i + 3) * KC);
        }
        const u32 bb = ring + (i % 3) * BUFSZ;
        #pragma unroll
        for (int ks = 0; ks < 2; ks++) {
            u32 ah[4], al[4];
            u32 aaddr = aoff(arow, (u32)(ks * 16) + akof);
            LDMX4(ah[0], ah[1], ah[2], ah[3], bb + BUF_A_HI + aaddr);
            LDMX4(al[0], al[1], al[2], al[3], bb + BUF_A_LO + aaddr);
            u32 bh[16], bl[16];
            #pragma unroll
            for (int g = 0; g < 4; g++) {
                u32 baddr = aoff((u32)(g * 16) + brow_base, (u32)(ks * 16) + bkof);
                LDMX4(bh[4 * g], bh[4 * g + 1], bh[4 * g + 2], bh[4 * g + 3], bb + BUF_B_HI + baddr);
                LDMX4(bl[4 * g], bl[4 * g + 1], bl[4 * g + 2], bl[4 * g + 3], bb + BUF_B_LO + baddr);
            }
            #pragma unroll
            for (int nt = 0; nt < 8; nt++) {
                MMA16816(acc[nt], ah, bh[2 * nt], bh[2 * nt + 1]);
                MMA16816(acc[nt], ah, bl[2 * nt], bl[2 * nt + 1]);
                MMA16816(acc[nt], al, bh[2 * nt], bh[2 * nt + 1]);
            }
        }
        __syncthreads();
    }

    // ---- gemm partial: relu(acc + b1) . Wf, reduce over 4-lane column group ----
    float o[2][3] = {{0.f, 0.f, 0.f}, {0.f, 0.f, 0.f}};
    #pragma unroll
    for (int nt = 0; nt < 8; nt++) {
        const int n0 = nt * 8 + 2 * (lane & 3);
        const int n1 = n0 + 1;
        const float bb0 = sB1[n0], bb1 = sB1[n1];
        float c00 = acc[nt][0] + bb0; c00 = c00 > 0.f ? c00 : 0.f;
        float c01 = acc[nt][1] + bb1; c01 = c01 > 0.f ? c01 : 0.f;
        float c10 = acc[nt][2] + bb0; c10 = c10 > 0.f ? c10 : 0.f;
        float c11 = acc[nt][3] + bb1; c11 = c11 > 0.f ? c11 : 0.f;
        #pragma unroll
        for (int j = 0; j < 3; j++) {
            o[0][j] += c00 * sWf[j * 64 + n0] + c01 * sWf[j * 64 + n1];
            o[1][j] += c10 * sWf[j * 64 + n0] + c11 * sWf[j * 64 + n1];
        }
    }
    #pragma unroll
    for (int r = 0; r < 2; r++)
        #pragma unroll
        for (int j = 0; j < 3; j++) {
            o[r][j] += __shfl_xor_sync(0xFFFFFFFFu, o[r][j], 1);
            o[r][j] += __shfl_xor_sync(0xFFFFFFFFu, o[r][j], 2);
        }

    // ---- copy G tables into the dead ring ----
    float* sGr = (float*)rbase;            // 16KB
    float* sGi = sGr + 4096;               // 16KB
    {
        const float4* gr4 = (const float4*)g_Gr;
        const float4* gi4 = (const float4*)g_Gi;
        float4* dr = (float4*)sGr;
        float4* di = (float4*)sGi;
        for (int i = tid; i < 1024; i += 128) { dr[i] = gr4[i]; di[i] = gi4[i]; }
    }
    __syncthreads();

    // ---- quantum part: 2 threads per sample, s-range split ----
    {
        const int sl = tid >> 1;
        const int half = tid & 1;
        const int sample = row0 + sl;
        float csq[NQ], snq[NQ];
        #pragma unroll
        for (int q = 0; q < NQ; q++) sincosf(0.5f * xq[sample * NQ + q], &snq[q], &csq[q]);

        float a[64];
        a[0] = csq[0]; a[1] = snq[0];
        #pragma unroll
        for (int q = 1; q < NQ; q++) {
            const int n = 1 << q;
            #pragma unroll 32
            for (int j = n - 1; j >= 0; j--) {
                float v = a[j];
                a[2 * j]     = v * csq[q];
                a[2 * j + 1] = v * snq[q];
            }
        }

        float q0 = 0.f, q1 = 0.f, q2 = 0.f;
        const int s0 = half * 32;
        #pragma unroll 2
        for (int ss = 0; ss < 32; ss++) {
            const int s = s0 + ss;
            const float4* gr = (const float4*)(sGr + s * 64);
            const float4* gi = (const float4*)(sGi + s * 64);
            float yr0 = 0.f, yr1 = 0.f, yi0 = 0.f, yi1 = 0.f;
            #pragma unroll
            for (int t4 = 0; t4 < 16; t4++) {
                float4 g1 = gr[t4], g2 = gi[t4];
                const float* av = &a[t4 * 4];
                yr0 += g1.x * av[0]; yr1 += g1.y * av[1];
                yr0 += g1.z * av[2]; yr1 += g1.w * av[3];
                yi0 += g2.x * av[0]; yi1 += g2.y * av[1];
                yi0 += g2.z * av[2]; yi1 += g2.w * av[3];
            }
            float yr = yr0 + yr1, yi = yi0 + yi1;
            float p = yr * yr + yi * yi;
            q0 += p * sG[s];
            q1 += p * sG[64 + s];
            q2 += p * sG[128 + s];
        }
        q0 += __shfl_xor_sync(0xFFFFFFFFu, q0, 1);
        q1 += __shfl_xor_sync(0xFFFFFFFFu, q1, 1);
        q2 += __shfl_xor_sync(0xFFFFFFFFu, q2, 1);
        if (half == 0) {
            sQ[sl * 3 + 0] = q0 + sd[0];
            sQ[sl * 3 + 1] = q1 + sd[1];
            sQ[sl * 3 + 2] = q2 + sd[2];
        }
    }
    __syncthreads();

    if ((lane & 3) == 0) {
        const int lr0 = m0 + (lane >> 2);
        const int gr0 = row0 + lr0;
        #pragma unroll
        for (int j = 0; j < 3; j++) {
            out[(size_t)gr0 * 3 + j]       = o[0][j] + sQ[lr0 * 3 + j];
            out[(size_t)(gr0 + 8) * 3 + j] = o[1][j] + sQ[(lr0 + 8) * 3 + j];
        }
    }
}

// ==================== launch ====================
extern "C" void kernel_launch(void* const* d_in, const int* in_sizes, int n_in,
                              void* d_out, int out_size) {
    const float* xc = (const float*)d_in[0];
    const float* xq = (const float*)d_in[1];
    const float* W1 = (const float*)d_in[2];
    const float* b1 = (const float*)d_in[3];
    const float* qw = (const float*)d_in[4];
    const float* Wq = (const float*)d_in[5];
    const float* bq = (const float*)d_in[6];
    const float* Wf = (const float*)d_in[7];
    const float* bf = (const float*)d_in[8];
    float* out = (float*)d_out;

    const int B = in_sizes[0] / 2048;  // 16384

    static int configured = 0;
    if (!configured) {
        cudaFuncSetAttribute(fused_kernel, cudaFuncAttributeMaxDynamicSharedMemorySize, GEMM_DSMEM);
        configured = 1;
    }

    precompute_kernel<<<4, 256>>>(qw, Wq, bq, Wf, bf);
    fused_kernel<<<B / 64, 128, GEMM_DSMEM>>>(xc, W1, b1, Wf, xq, out);
}